// round 8
// baseline (speedup 1.0000x reference)
#include <cuda_runtime.h>

// SKA: out[b, g*32+c, h, w] = sum_{di,dj} x[b, g*32+c, h+di-2, w+dj-2] * w[b, g, di*5+dj, h, w]
// x [8,256,64,64] f32, w [8,8,25,64,64] f32, out [8,256,64,64] f32.
//
// Single launch (no interior/edge split — the 128-block edge kernel in R7 added a
// 10.6us serialized tail). Thread = 4px x 2ch x 2rows. Warp = 8wq x 4cpi -> each
// w LDS.128 is one conflict-free 128B broadcast wavefront. w tile [25][2][64] in
// smem. x loads double-buffered; all inner addresses are immediate offsets off
// single base pointers; vertical edges handled by per-row predicated zero-fill.

#define B_  8
#define C_  256
#define H_  64
#define W_  64
#define G_  8
#define CG_ 32
#define NC_ 2
#define RH_ 2
#define HW_ (H_ * W_)

__global__ __launch_bounds__(256, 4)
void SKA_60387240182286_kernel(const float* __restrict__ x,
                               const float* __restrict__ wgt,
                               float* __restrict__ out)
{
    __shared__ float ws[25 * RH_ * W_];   // [k][rr][w] = 12.8 KB

    const int tid    = threadIdx.x;
    const int lane   = tid & 31;
    const int warp   = tid >> 5;
    const int wq_lo  = lane & 7;
    const int cpi_lo = lane >> 3;
    const int wq_hi  = warp & 1;
    const int cpi_hi = warp >> 1;
    const int wq  = wq_lo + 8 * wq_hi;    // 0..15
    const int cpi = cpi_lo + 4 * cpi_hi;  // 0..15

    const int bg = blockIdx.x;            // b*8 + g
    const int h0 = blockIdx.y * RH_;
    const int b  = bg >> 3;
    const int g  = bg & 7;
    const int w0 = wq * 4;
    const int c0 = g * CG_ + cpi * NC_;

    // ---- stage w tile: rows h0..h0+1, all 25 taps
    {
        const float* wsrc = wgt + (((size_t)bg * 25) * H_ + h0) * W_;
        float4* wsv = (float4*)ws;
#pragma unroll
        for (int i = tid; i < 800; i += 256) {
            const int k = i >> 5;
            const int r = i & 31;
            wsv[i] = *(const float4*)(wsrc + (size_t)k * HW_ + r * 4);
        }
    }
    __syncthreads();

    // single bases; all per-(c,hi)/(k,rr) offsets are compile-time immediates
    const float* xb  = x + (((size_t)(b * C_ + c0)) * H_ + (h0 - 2)) * W_ + w0;
    const float* wsb = ws + w0;

    float acc[RH_][NC_][4];
#pragma unroll
    for (int r = 0; r < RH_; ++r)
#pragma unroll
        for (int c = 0; c < NC_; ++c) {
            acc[r][c][0] = 0.f; acc[r][c][1] = 0.f;
            acc[r][c][2] = 0.f; acc[r][c][3] = 0.f;
        }

    const float2 z2 = make_float2(0.f, 0.f);
    const float4 z4 = make_float4(0.f, 0.f, 0.f, 0.f);
    const bool left_edge  = (wq == 0);
    const bool right_edge = (wq == 15);

    float xv[2][NC_][8];                  // double-buffered window, cols [w0-2, w0+5]

    // prologue: row hi=0 (hy = h0-2)
    {
        const bool rv = (h0 - 2 >= 0);
#pragma unroll
        for (int c = 0; c < NC_; ++c) {
            const float* p = xb + c * HW_;
            float2 a = (rv && !left_edge)  ? *(const float2*)(p - 2) : z2;
            float4 m = rv                  ? *(const float4*)(p)     : z4;
            float2 r = (rv && !right_edge) ? *(const float2*)(p + 4) : z2;
            xv[0][c][0] = a.x; xv[0][c][1] = a.y;
            xv[0][c][2] = m.x; xv[0][c][3] = m.y; xv[0][c][4] = m.z; xv[0][c][5] = m.w;
            xv[0][c][6] = r.x; xv[0][c][7] = r.y;
        }
    }

#pragma unroll
    for (int hi = 0; hi < RH_ + 4; ++hi) {
        const int cur = hi & 1;
        const int nxt = cur ^ 1;

        // prefetch row hi+1
        if (hi < RH_ + 3) {
            const int hyn = h0 - 1 + hi;
            const bool rvn = (hyn >= 0) && (hyn < H_);
#pragma unroll
            for (int c = 0; c < NC_; ++c) {
                const float* p = xb + c * HW_ + (hi + 1) * W_;
                float2 a = (rvn && !left_edge)  ? *(const float2*)(p - 2) : z2;
                float4 m = rvn                  ? *(const float4*)(p)     : z4;
                float2 r = (rvn && !right_edge) ? *(const float2*)(p + 4) : z2;
                xv[nxt][c][0] = a.x; xv[nxt][c][1] = a.y;
                xv[nxt][c][2] = m.x; xv[nxt][c][3] = m.y;
                xv[nxt][c][4] = m.z; xv[nxt][c][5] = m.w;
                xv[nxt][c][6] = r.x; xv[nxt][c][7] = r.y;
            }
        }

        // compute with row hi
#pragma unroll
        for (int rr = 0; rr < RH_; ++rr) {
            const int di = hi - rr;
            if (di < 0 || di > 4) continue;       // compile-time prune
#pragma unroll
            for (int dj = 0; dj < 5; ++dj) {
                const int k = di * 5 + dj;
                const float4 wv = *(const float4*)(wsb + (k * RH_ + rr) * W_);
#pragma unroll
                for (int c = 0; c < NC_; ++c) {
                    acc[rr][c][0] = fmaf(xv[cur][c][dj + 0], wv.x, acc[rr][c][0]);
                    acc[rr][c][1] = fmaf(xv[cur][c][dj + 1], wv.y, acc[rr][c][1]);
                    acc[rr][c][2] = fmaf(xv[cur][c][dj + 2], wv.z, acc[rr][c][2]);
                    acc[rr][c][3] = fmaf(xv[cur][c][dj + 3], wv.w, acc[rr][c][3]);
                }
            }
        }
    }

    float* ob = out + (((size_t)(b * C_ + c0)) * H_ + h0) * W_ + w0;
#pragma unroll
    for (int r = 0; r < RH_; ++r)
#pragma unroll
        for (int c = 0; c < NC_; ++c) {
            *(float4*)(ob + c * HW_ + r * W_) =
                make_float4(acc[r][c][0], acc[r][c][1], acc[r][c][2], acc[r][c][3]);
        }
}

extern "C" void kernel_launch(void* const* d_in, const int* in_sizes, int n_in,
                              void* d_out, int out_size)
{
    const float* x   = (const float*)d_in[0];
    const float* wgt = (const float*)d_in[1];
    float* out = (float*)d_out;

    dim3 grid(B_ * G_, H_ / RH_);   // (64, 32) = 2048 blocks, one launch
    SKA_60387240182286_kernel<<<grid, 256>>>(x, wgt, out);
}

// round 9
// speedup vs baseline: 1.6086x; 1.6086x over previous
#include <cuda_runtime.h>

// SKA: out[b, g*32+c, h, w] = sum_{di,dj} x[b, g*32+c, h+di-2, w+dj-2] * w[b, g, di*5+dj, h, w]
// x [8,256,64,64] f32, w [8,8,25,64,64] f32, out [8,256,64,64] f32.
//
// Thread = 4px x 4ch x 2rows (32 outputs). Warp = 16wq x 2 channel-slots; the two
// 16-lane shfl segments are the slots, so x halos come from lane+-1 via
// __shfl_{up,down}_sync(width=16) after ONE aligned LDG.128 per (c,row) —
// no f2 halo loads. w tile [25][4rows][64] in smem (block spans 2 hpairs via a
// warp bit); each w LDS.128 is 2 wavefronts and feeds 16 FMAs. All inner offsets
// are compile-time immediates. True image edges coincide with shfl segment
// boundaries and are zeroed by the same predicates.

#define B_  8
#define C_  256
#define H_  64
#define W_  64
#define G_  8
#define CG_ 32
#define HW_ (H_ * W_)

__global__ __launch_bounds__(256, 3)
void SKA_60387240182286_kernel(const float* __restrict__ x,
                               const float* __restrict__ wgt,
                               float* __restrict__ out)
{
    __shared__ float ws[25 * 4 * W_];     // [k][4 rows][64] = 25.6 KB

    const int tid  = threadIdx.x;
    const int lane = tid & 31;
    const int warp = tid >> 5;            // 0..7
    const int wq      = lane & 15;        // 0..15: 4-wide pixel group
    const int slot_lo = lane >> 4;        // 0..1: shfl segment = channel-slot bit
    const int slot = slot_lo + 2 * (warp & 3);  // 0..7: 4-channel slot
    const int hsub = warp >> 2;           // 0..1: which hpair of the block

    const int bg  = blockIdx.x;           // b*8 + g
    const int b   = bg >> 3;
    const int g   = bg & 7;
    const int h0b = blockIdx.y * 4;       // block covers 4 output rows
    const int h0  = h0b + hsub * 2;       // this warp's 2-row base
    const int w0  = wq * 4;
    const int c0  = g * CG_ + slot * 4;

    // ---- stage w tile: rows h0b..h0b+3, all 25 taps
    {
        const float* wsrc = wgt + ((size_t)bg * 25 * H_ + h0b) * W_;
        float4* wsv = (float4*)ws;
#pragma unroll
        for (int i = tid; i < 1600; i += 256) {     // 1600 float4
            const int k   = i >> 6;                  // 64 f4 per tap (4 rows x 16)
            const int rem = i & 63;
            wsv[i] = *(const float4*)(wsrc + (size_t)k * HW_ +
                                      (rem >> 4) * W_ + (rem & 15) * 4);
        }
    }
    __syncthreads();

    const float* xb  = x + (((size_t)(b * C_ + c0)) * H_ + (h0 - 2)) * W_ + w0;
    const float* wsb = ws + (hsub * 2) * W_ + w0;   // + (k*4+rr)*W_ immediates

    float acc[2][4][4];                   // [rr][c][px]
#pragma unroll
    for (int r = 0; r < 2; ++r)
#pragma unroll
        for (int c = 0; c < 4; ++c) {
            acc[r][c][0] = 0.f; acc[r][c][1] = 0.f;
            acc[r][c][2] = 0.f; acc[r][c][3] = 0.f;
        }

    const float4 z4 = make_float4(0.f, 0.f, 0.f, 0.f);
    const bool le = (wq == 0);
    const bool re = (wq == 15);

#pragma unroll
    for (int hi = 0; hi < 6; ++hi) {                // x row hy = h0 - 2 + hi
        const int hy = h0 - 2 + hi;
        const bool rv = (hy >= 0) && (hy < H_);     // warp-uniform

        // window xw[c][0..7] covers cols [w0-2 .. w0+5]
        float xw[4][8];
#pragma unroll
        for (int c = 0; c < 4; ++c) {
            const float4 m = rv ? *(const float4*)(xb + c * HW_ + hi * W_) : z4;
            const float lz = __shfl_up_sync(0xFFFFFFFFu, m.z, 1, 16);
            const float lw = __shfl_up_sync(0xFFFFFFFFu, m.w, 1, 16);
            const float rx = __shfl_down_sync(0xFFFFFFFFu, m.x, 1, 16);
            const float ry = __shfl_down_sync(0xFFFFFFFFu, m.y, 1, 16);
            xw[c][0] = le ? 0.f : lz;
            xw[c][1] = le ? 0.f : lw;
            xw[c][2] = m.x; xw[c][3] = m.y; xw[c][4] = m.z; xw[c][5] = m.w;
            xw[c][6] = re ? 0.f : rx;
            xw[c][7] = re ? 0.f : ry;
        }

        // x row hi feeds output row rr where di = hi - rr in [0,4]
#pragma unroll
        for (int rr = 0; rr < 2; ++rr) {
            const int di = hi - rr;
            if (di < 0 || di > 4) continue;         // compile-time prune
#pragma unroll
            for (int dj = 0; dj < 5; ++dj) {
                const int k = di * 5 + dj;
                const float4 wv = *(const float4*)(wsb + (k * 4 + rr) * W_);
#pragma unroll
                for (int c = 0; c < 4; ++c) {
                    // out px p (col w0+p), tap dj -> window idx p+dj
                    acc[rr][c][0] = fmaf(xw[c][dj + 0], wv.x, acc[rr][c][0]);
                    acc[rr][c][1] = fmaf(xw[c][dj + 1], wv.y, acc[rr][c][1]);
                    acc[rr][c][2] = fmaf(xw[c][dj + 2], wv.z, acc[rr][c][2]);
                    acc[rr][c][3] = fmaf(xw[c][dj + 3], wv.w, acc[rr][c][3]);
                }
            }
        }
    }

    float* ob = out + (((size_t)(b * C_ + c0)) * H_ + h0) * W_ + w0;
#pragma unroll
    for (int rr = 0; rr < 2; ++rr)
#pragma unroll
        for (int c = 0; c < 4; ++c) {
            *(float4*)(ob + c * HW_ + rr * W_) =
                make_float4(acc[rr][c][0], acc[rr][c][1],
                            acc[rr][c][2], acc[rr][c][3]);
        }
}

extern "C" void kernel_launch(void* const* d_in, const int* in_sizes, int n_in,
                              void* d_out, int out_size)
{
    const float* x   = (const float*)d_in[0];
    const float* wgt = (const float*)d_in[1];
    float* out = (float*)d_out;

    dim3 grid(B_ * G_, H_ / 4);   // (64, 16) = 1024 blocks
    SKA_60387240182286_kernel<<<grid, 256>>>(x, wgt, out);
}